// round 9
// baseline (speedup 1.0000x reference)
#include <cuda_runtime.h>
#include <cuda_bf16.h>
#include <cstdint>

// Problem constants (shapes are fixed by the dataset)
#define MAX_N 100000
#define MAX_E 1000000

// Scratch: __device__ globals (no runtime allocation allowed)
__device__ float g_xl[MAX_N * 128];      // raw @ Wl
__device__ float g_xr[MAX_N * 128];      // raw @ Wr
__device__ float g_skip[MAX_N * 128];    // raw @ Ws + bs
__device__ int   g_deg[MAX_N];           // in-degree (excl. self-loop)
__device__ int   g_off[MAX_N];           // CSR offsets
__device__ int   g_cur[MAX_N];           // scatter cursors
__device__ int   g_csr[MAX_E];           // src ids grouped by dst
__device__ int   g_is64;                 // edge_index dtype flag (1 = int64)
// W^T in bf16 hi/lo split, XOR-swizzled [n][128] layout, 3 matrices
__device__ __nv_bfloat16 g_Bth[3 * 128 * 128];
__device__ __nv_bfloat16 g_Btl[3 * 128 * 128];

// ===================== PTX helpers (base ISA only) =========================
__device__ __forceinline__ uint32_t smem_u32(const void* p) {
    uint32_t a;
    asm("{ .reg .u64 t; cvta.to.shared.u64 t, %1; cvt.u32.u64 %0, t; }"
        : "=r"(a) : "l"(p));
    return a;
}
#define LDSM_X4(r0, r1, r2, r3, addr) \
    asm volatile("ldmatrix.sync.aligned.m8n8.x4.shared.b16 {%0,%1,%2,%3}, [%4];" \
                 : "=r"(r0), "=r"(r1), "=r"(r2), "=r"(r3) : "r"(addr))
#define MMA_BF16(d, a, b) \
    asm volatile("mma.sync.aligned.m16n8k16.row.col.f32.bf16.bf16.f32 " \
                 "{%0,%1,%2,%3}, {%4,%5,%6,%7}, {%8,%9}, {%0,%1,%2,%3};" \
                 : "+f"((d)[0]), "+f"((d)[1]), "+f"((d)[2]), "+f"((d)[3]) \
                 : "r"((a)[0]), "r"((a)[1]), "r"((a)[2]), "r"((a)[3]), \
                   "r"((b)[0]), "r"((b)[1]))

// Bijective XOR swizzle within [rows][128] bf16 tile (row stride 256B):
// chunk 0..15 -> (chunk&8) | ((chunk^r)&7); ldmatrix conflict-free.
__device__ __forceinline__ int swz(int r, int k) {
    int c = k >> 3;
    int sc = (c & 8) | ((c ^ r) & 7);
    return r * 128 + sc * 8 + (k & 7);
}

// ======================= dtype detect + edge fetch =========================
__global__ void k_detect(const unsigned int* __restrict__ p) {
    unsigned int v = 0;
    for (int i = threadIdx.x; i < 128; i += 32) v |= p[2 * i + 1];
    v |= __shfl_xor_sync(0xffffffffu, v, 16);
    v |= __shfl_xor_sync(0xffffffffu, v, 8);
    v |= __shfl_xor_sync(0xffffffffu, v, 4);
    v |= __shfl_xor_sync(0xffffffffu, v, 2);
    v |= __shfl_xor_sync(0xffffffffu, v, 1);
    if (threadIdx.x == 0) g_is64 = (v == 0u) ? 1 : 0;
}

__device__ __forceinline__ int fetch_idx(const void* ei, long long pos, int n) {
    int v;
    if (g_is64) v = (int)((const long long*)ei)[pos];
    else        v = ((const int*)ei)[pos];
    return min(max(v, 0), n - 1);
}

// ======================= CSR build (counting sort) =========================
__global__ void k_zero_deg(int n) {
    int i = blockIdx.x * blockDim.x + threadIdx.x;
    if (i < n) g_deg[i] = 0;
}

__global__ void k_hist(const void* __restrict__ ei, int E, int n) {
    int i = blockIdx.x * blockDim.x + threadIdx.x;
    if (i >= E) return;
    int d = fetch_idx(ei, (long long)E + i, n);
    atomicAdd(&g_deg[d], 1);
}

// Single-block exclusive scan over g_deg -> g_off (and g_cur copy)
__global__ void k_scan(int n) {
    __shared__ int part[1024];
    const int t = threadIdx.x;
    const int chunk = (n + 1023) / 1024;
    const int lo = t * chunk;
    const int hi = min(lo + chunk, n);
    int sum = 0;
    for (int i = lo; i < hi; i++) sum += g_deg[i];
    part[t] = sum;
    __syncthreads();
    for (int ofs = 1; ofs < 1024; ofs <<= 1) {
        int v = (t >= ofs) ? part[t - ofs] : 0;
        __syncthreads();
        part[t] += v;
        __syncthreads();
    }
    int base = (t == 0) ? 0 : part[t - 1];
    for (int i = lo; i < hi; i++) {
        g_off[i] = base;
        g_cur[i] = base;
        base += g_deg[i];
    }
}

__global__ void k_scatter(const void* __restrict__ ei, int E, int n) {
    int i = blockIdx.x * blockDim.x + threadIdx.x;
    if (i >= E) return;
    int s = fetch_idx(ei, i, n);
    int d = fetch_idx(ei, (long long)E + i, n);
    int pos = atomicAdd(&g_cur[d], 1);
    g_csr[pos] = s;
}

// ---------------------------------------------------------------------------
// Prep: W^T (=Bt[n][k]) in bf16 hi/lo, XOR-swizzled [128][128] tiles.
// ---------------------------------------------------------------------------
__global__ void k_prep(const float* __restrict__ Wl, const float* __restrict__ Wr,
                       const float* __restrict__ Ws) {
    int i = blockIdx.x * blockDim.x + threadIdx.x;
    if (i >= 3 * 16384) return;
    int m = i >> 14, kk = (i >> 7) & 127, nn = i & 127;
    const float* W = (m == 0) ? Wl : ((m == 1) ? Wr : Ws);
    float v = W[kk * 128 + nn];
    __nv_bfloat16 h = __float2bfloat16(v);
    __nv_bfloat16 l = __float2bfloat16(v - __bfloat162float(h));
    int idx = m * 16384 + swz(nn, kk);
    g_Bth[idx] = h;
    g_Btl[idx] = l;
}

// ---------------------------------------------------------------------------
// Tensor-core GEMM via mma.sync bf16 split (unchanged from R8).
// ---------------------------------------------------------------------------
#define SM_AH 0
#define SM_AL 16384
#define SM_BH 32768
#define SM_BL 65536
#define SM_TOTAL 98304

__global__ void __launch_bounds__(256, 2)
k_gemm_mma(const float* __restrict__ x, const float* __restrict__ tf,
           const float* __restrict__ bs, int n) {
    extern __shared__ char smem[];
    const uint32_t sbase = smem_u32(smem);
    const int tid = threadIdx.x;
    const int row0 = blockIdx.x * 64;

    {
        __nv_bfloat16* sh = reinterpret_cast<__nv_bfloat16*>(smem + SM_AH);
        __nv_bfloat16* sl = reinterpret_cast<__nv_bfloat16*>(smem + SM_AL);
        for (int i = tid; i < 64 * 128; i += 256) {
            int r = i >> 7, k = i & 127;
            int g = row0 + r;
            float v = 0.f;
            if (g < n) v = (k < 126) ? x[g * 126 + k] : tf[g * 2 + (k - 126)];
            __nv_bfloat16 h = __float2bfloat16(v);
            __nv_bfloat16 l = __float2bfloat16(v - __bfloat162float(h));
            int idx = swz(r, k);
            sh[idx] = h;
            sl[idx] = l;
        }
    }

    const int wid = tid >> 5;
    const int lane = tid & 31;
    const int wm = wid >> 1;
    const int wn = wid & 1;
    const int r0 = wm * 16;
    const int c0 = wn * 64;
    const int sub = lane >> 3;
    const int rin = lane & 7;

    for (int which = 0; which < 3; which++) {
        float* out = (which == 0) ? g_xl : ((which == 1) ? g_xr : g_skip);

        {
            const uint4* gh = reinterpret_cast<const uint4*>(&g_Bth[which * 16384]);
            const uint4* gl = reinterpret_cast<const uint4*>(&g_Btl[which * 16384]);
            uint4* sh = reinterpret_cast<uint4*>(smem + SM_BH);
            uint4* sl = reinterpret_cast<uint4*>(smem + SM_BL);
            for (int i = tid; i < 2048; i += 256) { sh[i] = gh[i]; sl[i] = gl[i]; }
        }
        __syncthreads();

        float acc[8][4];
#pragma unroll
        for (int nt = 0; nt < 8; nt++)
#pragma unroll
            for (int q = 0; q < 4; q++) acc[nt][q] = 0.f;

#pragma unroll
        for (int ks = 0; ks < 8; ks++) {
            uint32_t ah[4], al[4], bh[8][2], bl[8][2];
            {
                const int ar = r0 + (sub & 1) * 8 + rin;
                const int ac = ks * 2 + (sub >> 1);
                const uint32_t off =
                    (uint32_t)(ar * 256 + (((ac & 8) | ((ac ^ ar) & 7)) << 4));
                LDSM_X4(ah[0], ah[1], ah[2], ah[3], sbase + SM_AH + off);
                LDSM_X4(al[0], al[1], al[2], al[3], sbase + SM_AL + off);
            }
#pragma unroll
            for (int nt2 = 0; nt2 < 4; nt2++) {
                const int br = c0 + nt2 * 16 + (sub >> 1) * 8 + rin;
                const int bc = ks * 2 + (sub & 1);
                const uint32_t off =
                    (uint32_t)(br * 256 + (((bc & 8) | ((bc ^ br) & 7)) << 4));
                uint32_t q0, q1, q2, q3;
                LDSM_X4(q0, q1, q2, q3, sbase + SM_BH + off);
                bh[nt2 * 2][0] = q0;     bh[nt2 * 2][1] = q1;
                bh[nt2 * 2 + 1][0] = q2; bh[nt2 * 2 + 1][1] = q3;
                LDSM_X4(q0, q1, q2, q3, sbase + SM_BL + off);
                bl[nt2 * 2][0] = q0;     bl[nt2 * 2][1] = q1;
                bl[nt2 * 2 + 1][0] = q2; bl[nt2 * 2 + 1][1] = q3;
            }
#pragma unroll
            for (int nt = 0; nt < 8; nt++) {
                MMA_BF16(acc[nt], ah, bh[nt]);
                MMA_BF16(acc[nt], ah, bl[nt]);
                MMA_BF16(acc[nt], al, bh[nt]);
            }
        }

#pragma unroll
        for (int nt = 0; nt < 8; nt++) {
            const int col = c0 + nt * 8 + (lane & 3) * 2;
            float b0 = 0.f, b1 = 0.f;
            if (which == 2) { b0 = bs[col]; b1 = bs[col + 1]; }
            const int ra = row0 + r0 + (lane >> 2);
            if (ra < n) {
                float2 v = make_float2(acc[nt][0] + b0, acc[nt][1] + b1);
                *reinterpret_cast<float2*>(&out[ra * 128 + col]) = v;
            }
            const int rb = ra + 8;
            if (rb < n) {
                float2 v = make_float2(acc[nt][2] + b0, acc[nt][3] + b1);
                *reinterpret_cast<float2*>(&out[rb * 128 + col]) = v;
            }
        }
        __syncthreads();
    }
}

// ---------------------------------------------------------------------------
// Fused GAT aggregation + readout, one WARP per destination node.
// For node d: iterate self-loop + CSR in-edges; per edge:
//   e[h] = att . lrelu(xl[s] + xr[d]);  ee = exp(e)
//   denom += ee (register);  acc += ee * xl[s] (register)
// Then: c = acc/denom + bias_gat + skip;  elu; out[d] = sigmoid(c.Wo + bo).
// No atomics, no agg/denom buffers, no separate final kernel.
// ---------------------------------------------------------------------------
__global__ void __launch_bounds__(256)
k_gat(const float* __restrict__ att, const float* __restrict__ bias_gat,
      const float* __restrict__ Wo, const float* __restrict__ bo,
      float* __restrict__ out, int n) {
    const int node = blockIdx.x * 8 + (threadIdx.x >> 5);
    const int lane = threadIdx.x & 31;
    if (node >= n) return;

    const float4 xr4 = *reinterpret_cast<const float4*>(&g_xr[node * 128 + lane * 4]);
    const float4 at4 = *reinterpret_cast<const float4*>(&att[lane * 4]);

    const int off = g_off[node];
    const int deg = g_deg[node];

    float4 acc = make_float4(0.f, 0.f, 0.f, 0.f);
    float denom = 0.f;

    // Batched index load (covers deg<=32; rare tail handled in-loop)
    int si = (lane < deg) ? g_csr[off + lane] : 0;

    int s = node;  // self-loop first
    float4 xl = *reinterpret_cast<const float4*>(&g_xl[s * 128 + lane * 4]);

    for (int j = 0; j <= deg; j++) {
        // prefetch next edge's xl while computing current (MLP=2)
        float4 xl_nx = make_float4(0.f, 0.f, 0.f, 0.f);
        if (j < deg) {
            int s_nx = (j < 32) ? __shfl_sync(0xffffffffu, si, j) : g_csr[off + j];
            xl_nx = *reinterpret_cast<const float4*>(&g_xl[s_nx * 128 + lane * 4]);
        }

        float m, p = 0.f;
        m = xl.x + xr4.x; p += (m > 0.f ? m : 0.2f * m) * at4.x;
        m = xl.y + xr4.y; p += (m > 0.f ? m : 0.2f * m) * at4.y;
        m = xl.z + xr4.z; p += (m > 0.f ? m : 0.2f * m) * at4.z;
        m = xl.w + xr4.w; p += (m > 0.f ? m : 0.2f * m) * at4.w;
        // reduce within 4-lane head group
        p += __shfl_xor_sync(0xffffffffu, p, 1);
        p += __shfl_xor_sync(0xffffffffu, p, 2);

        const float ee = expf(p);   // softmax-max dropped: |e| bounded
        denom += ee;
        acc.x += ee * xl.x;
        acc.y += ee * xl.y;
        acc.z += ee * xl.z;
        acc.w += ee * xl.w;

        xl = xl_nx;
    }

    const float dn = 1.f / (denom + 1e-16f);
    const float4 sk = *reinterpret_cast<const float4*>(&g_skip[node * 128 + lane * 4]);
    const float4 bg = *reinterpret_cast<const float4*>(&bias_gat[lane * 4]);
    const float4 ww = *reinterpret_cast<const float4*>(&Wo[lane * 4]);

    float c, p = 0.f;
    c = acc.x * dn + sk.x + bg.x; c = (c > 0.f) ? c : expm1f(c); p += c * ww.x;
    c = acc.y * dn + sk.y + bg.y; c = (c > 0.f) ? c : expm1f(c); p += c * ww.y;
    c = acc.z * dn + sk.z + bg.z; c = (c > 0.f) ? c : expm1f(c); p += c * ww.z;
    c = acc.w * dn + sk.w + bg.w; c = (c > 0.f) ? c : expm1f(c); p += c * ww.w;

    p += __shfl_xor_sync(0xffffffffu, p, 16);
    p += __shfl_xor_sync(0xffffffffu, p, 8);
    p += __shfl_xor_sync(0xffffffffu, p, 4);
    p += __shfl_xor_sync(0xffffffffu, p, 2);
    p += __shfl_xor_sync(0xffffffffu, p, 1);

    if (lane == 0) {
        out[node] = 1.f / (1.f + expf(-(p + bo[0])));
    }
}

// ---------------------------------------------------------------------------
extern "C" void kernel_launch(void* const* d_in, const int* in_sizes, int n_in,
                              void* d_out, int out_size) {
    const float* x   = (const float*)d_in[0];   // [N,126]
    const float* tf  = (const float*)d_in[1];   // [N,2]
    const void*  ei  = d_in[2];                 // [2,E] int32 or int64
    const float* Wl  = (const float*)d_in[3];   // [128,128]
    const float* Wr  = (const float*)d_in[4];
    const float* att = (const float*)d_in[5];   // [8,16]
    const float* bg  = (const float*)d_in[6];   // [128]
    const float* Ws  = (const float*)d_in[7];
    const float* bs  = (const float*)d_in[8];
    const float* Wo  = (const float*)d_in[9];   // [128,1]
    const float* bo  = (const float*)d_in[10];  // [1]
    float* out = (float*)d_out;

    const int n = in_sizes[0] / 126;
    const int E = in_sizes[2] / 2;

    cudaFuncSetAttribute(k_gemm_mma, cudaFuncAttributeMaxDynamicSharedMemorySize,
                         SM_TOTAL);

    k_detect<<<1, 32>>>((const unsigned int*)ei);
    k_zero_deg<<<(n + 255) / 256, 256>>>(n);
    k_prep<<<(3 * 16384 + 255) / 256, 256>>>(Wl, Wr, Ws);

    k_hist<<<(E + 255) / 256, 256>>>(ei, E, n);
    k_scan<<<1, 1024>>>(n);
    k_scatter<<<(E + 255) / 256, 256>>>(ei, E, n);

    k_gemm_mma<<<(n + 63) / 64, 256, SM_TOTAL>>>(x, tf, bs, n);

    k_gat<<<(n + 7) / 8, 256>>>(att, bg, Wo, bo, out, n);
}